// round 1
// baseline (speedup 1.0000x reference)
#include <cuda_runtime.h>

#define B_DIM 128
#define C_DIM 2048
#define HW 196
#define NC 8
#define NM 4

// ---- scratch (__device__ globals; no allocation allowed) ----
__device__ float g_weff[C_DIM * NC];            // folded weights, layout [c][k]
__device__ float g_dbuf[B_DIM * 2 * C_DIM];     // d = [gap_x | gap_u], [b][4096]

// ============================================================================
// K0: fold ClassWisePool into conv weights.
// w_eff[c][k] = 0.25 * sum_j w_down[(4k+j)*C + c]
// ============================================================================
__global__ void k0_weff(const float* __restrict__ w_down) {
    int c = blockIdx.x * blockDim.x + threadIdx.x;
    if (c >= C_DIM) return;
#pragma unroll
    for (int k = 0; k < NC; ++k) {
        float s = 0.f;
#pragma unroll
        for (int j = 0; j < NM; ++j) s += w_down[(k * NM + j) * C_DIM + c];
        g_weff[c * NC + k] = 0.25f * s;
    }
}

// ============================================================================
// K1: per-batch block. Computes m_c[b,k,p] = sum_c w_eff[k,c]*x[b,c,p] + b_eff[k],
// then (fused, since this block owns the whole batch):
//   v[b,k] = mean_p m_c[b,k,p]
//   m[b,p] = (1/NC) * sum_k v[b,k]*m_c[b,k,p]
// 224 threads (7 warps); threads 0..195 own one pixel each, 8 fp32 accumulators.
// w_eff staged in smem in two 1024-channel halves (32 KB each).
// ============================================================================
__global__ void __launch_bounds__(224) k1_mc(
    const float* __restrict__ x,
    const float* __restrict__ b_down,
    float* __restrict__ out_v,       // [B][NC]
    float* __restrict__ out_m,       // [B][HW]
    float* __restrict__ out_mc)      // [B][NC][HW]
{
    __shared__ float wsh[1024 * NC];     // 32 KB
    __shared__ float red[NC * 225];      // m_c staging, padded rows (bank-safe)
    __shared__ float vsh[NC];
    __shared__ float besh[NC];

    const int b = blockIdx.x;
    const int t = threadIdx.x;
    const float* xb = x + (size_t)b * C_DIM * HW;

    float acc[NC];
#pragma unroll
    for (int k = 0; k < NC; ++k) acc[k] = 0.f;

    for (int half = 0; half < 2; ++half) {
        for (int i = t; i < 1024 * NC; i += 224)
            wsh[i] = g_weff[half * 1024 * NC + i];
        __syncthreads();

        if (t < HW) {
            const float* xp = xb + (size_t)half * 1024 * HW + t;
#pragma unroll 1
            for (int c = 0; c < 1024; c += 8) {
                float xv[8];
#pragma unroll
                for (int u = 0; u < 8; ++u) xv[u] = xp[(c + u) * HW];
#pragma unroll
                for (int u = 0; u < 8; ++u) {
                    float4 wa = *(const float4*)&wsh[(c + u) * NC];
                    float4 wb = *(const float4*)&wsh[(c + u) * NC + 4];
                    acc[0] = fmaf(xv[u], wa.x, acc[0]);
                    acc[1] = fmaf(xv[u], wa.y, acc[1]);
                    acc[2] = fmaf(xv[u], wa.z, acc[2]);
                    acc[3] = fmaf(xv[u], wa.w, acc[3]);
                    acc[4] = fmaf(xv[u], wb.x, acc[4]);
                    acc[5] = fmaf(xv[u], wb.y, acc[5]);
                    acc[6] = fmaf(xv[u], wb.z, acc[6]);
                    acc[7] = fmaf(xv[u], wb.w, acc[7]);
                }
            }
        }
        __syncthreads();
    }

    // folded bias
    if (t < NC)
        besh[t] = 0.25f * (b_down[4 * t] + b_down[4 * t + 1] +
                           b_down[4 * t + 2] + b_down[4 * t + 3]);
    __syncthreads();

    // finalize m_c: write to gmem + stage in smem for the v/m epilogue
    if (t < HW) {
#pragma unroll
        for (int k = 0; k < NC; ++k) {
            float val = acc[k] + besh[k];
            red[k * 225 + t] = val;
            out_mc[((size_t)b * NC + k) * HW + t] = val;
        }
    }
    __syncthreads();

    // v[k] = mean_p m_c[k][p]  (8 lanes of warp 0, serial sums, bank-conflict-free)
    if (t < NC) {
        float s = 0.f;
        for (int p = 0; p < HW; ++p) s += red[t * 225 + p];
        float vv = s * (1.0f / (float)HW);
        vsh[t] = vv;
        out_v[b * NC + t] = vv;
    }
    __syncthreads();

    // m[p] = (1/NC) sum_k v[k]*m_c[k][p]
    if (t < HW) {
        float s = 0.f;
#pragma unroll
        for (int k = 0; k < NC; ++k) s = fmaf(vsh[k], red[k * 225 + t], s);
        out_m[b * HW + t] = s * (1.0f / (float)NC);
    }
}

// ============================================================================
// K3: second pass over x. For each (b,c):
//   gap_x[b,c] = mean_p x[b,c,p]
//   gap_u[b,c] = mean_p m[b,p]*x[b,c,p]
// One warp per channel (lanes stride the 196-pixel row, coalesced).
// Grid (chunk=8, b=128), 256 threads = 8 warps, 32 channels per warp.
// ============================================================================
__global__ void __launch_bounds__(256) k3_gap(
    const float* __restrict__ x,
    const float* __restrict__ m_in)      // [B][HW], read from d_out
{
    __shared__ float msh[HW];
    const int chunk = blockIdx.x;
    const int b = blockIdx.y;
    const int t = threadIdx.x;
    if (t < HW) msh[t] = m_in[b * HW + t];
    __syncthreads();

    const int w = t >> 5, l = t & 31;
    const float* xb = x + (size_t)b * C_DIM * HW;

#pragma unroll 1
    for (int i = 0; i < 32; ++i) {
        int c = chunk * 256 + w * 32 + i;
        const float* row = xb + (size_t)c * HW;
        float s1 = 0.f, s2 = 0.f;
#pragma unroll
        for (int j = 0; j < 6; ++j) {
            float xv = row[l + 32 * j];
            s1 += xv;
            s2 = fmaf(xv, msh[l + 32 * j], s2);
        }
        if (l < 4) {
            float xv = row[l + 192];
            s1 += xv;
            s2 = fmaf(xv, msh[l + 192], s2);
        }
#pragma unroll
        for (int o = 16; o; o >>= 1) {
            s1 += __shfl_down_sync(0xffffffffu, s1, o);
            s2 += __shfl_down_sync(0xffffffffu, s2, o);
        }
        if (l == 0) {
            g_dbuf[(size_t)b * 2 * C_DIM + c]         = s1 * (1.0f / (float)HW);
            g_dbuf[(size_t)b * 2 * C_DIM + C_DIM + c] = s2 * (1.0f / (float)HW);
        }
    }
}

// ============================================================================
// K4: output[b,k] = sum_c w_cls[k,c]*d[b,c] + b_cls[k].  One block per batch.
// ============================================================================
__global__ void __launch_bounds__(256) k4_out(
    const float* __restrict__ w_cls,   // [NC][2C]
    const float* __restrict__ b_cls,   // [NC]
    float* __restrict__ out_output)    // [B][NC]
{
    const int b = blockIdx.x;
    const int t = threadIdx.x;
    const int lane = t & 31, warp = t >> 5;

    float acc[NC];
#pragma unroll
    for (int k = 0; k < NC; ++k) acc[k] = 0.f;

    const float* db = g_dbuf + (size_t)b * 2 * C_DIM;
#pragma unroll 1
    for (int c = t; c < 2 * C_DIM; c += 256) {
        float dv = db[c];
#pragma unroll
        for (int k = 0; k < NC; ++k)
            acc[k] = fmaf(dv, w_cls[k * 2 * C_DIM + c], acc[k]);
    }
#pragma unroll
    for (int o = 16; o; o >>= 1) {
#pragma unroll
        for (int k = 0; k < NC; ++k)
            acc[k] += __shfl_down_sync(0xffffffffu, acc[k], o);
    }

    __shared__ float part[8][NC];
    if (lane == 0) {
#pragma unroll
        for (int k = 0; k < NC; ++k) part[warp][k] = acc[k];
    }
    __syncthreads();
    if (t < NC) {
        float s = b_cls[t];
#pragma unroll
        for (int w2 = 0; w2 < 8; ++w2) s += part[w2][t];
        out_output[b * NC + t] = s;
    }
}

// ============================================================================
// kernel_launch: 4 launches on the default stream (graph-capturable, no sync,
// no allocation, no atomics -> deterministic).
// Output layout (flattened tuple, reference order):
//   v      [128,8]        @ 0
//   output [128,8]        @ 1024
//   m      [128,1,14,14]  @ 2048
//   m_c    [128,8,14,14]  @ 27136
// ============================================================================
extern "C" void kernel_launch(void* const* d_in, const int* in_sizes, int n_in,
                              void* d_out, int out_size) {
    const float* x      = (const float*)d_in[0];
    const float* w_down = (const float*)d_in[1];
    const float* b_down = (const float*)d_in[2];
    const float* w_cls  = (const float*)d_in[3];
    const float* b_cls  = (const float*)d_in[4];

    float* out        = (float*)d_out;
    float* out_v      = out;
    float* out_output = out + 1024;
    float* out_m      = out + 2048;
    float* out_mc     = out + 27136;

    k0_weff<<<8, 256>>>(w_down);
    k1_mc<<<B_DIM, 224>>>(x, b_down, out_v, out_m, out_mc);
    k3_gap<<<dim3(8, B_DIM), 256>>>(x, out_m);
    k4_out<<<B_DIM, 256>>>(w_cls, b_cls, out_output);
}

// round 2
// speedup vs baseline: 1.8804x; 1.8804x over previous
#include <cuda_runtime.h>

#define B_DIM 128
#define C_DIM 2048
#define HW 196
#define NC 8
#define NM 4
#define NOUT 24                    // 8 A (m_c pre-bias) + 8 Z + 8 Y
#define PART_N (B_DIM * HW)        // 25088 global pixel-batch indices
#define SLABS 4
#define CSLAB (C_DIM / SLABS)      // 512

// ---- scratch (__device__ globals; no allocation allowed) ----
// weights, per channel 24 floats: [0..7]=w_eff, [8..15]=w_cls[:, :C], [16..23]=w_cls[:, C:]
__device__ float g_wk[C_DIM * NOUT];
// slab-partial per-pixel outputs: [slab][out24][g]
__device__ float g_part[SLABS * NOUT * PART_N];

// ---------------- packed f32x2 helpers ----------------
__device__ __forceinline__ unsigned long long fma2(
    unsigned long long a, unsigned long long b, unsigned long long c) {
    unsigned long long d;
    asm("fma.rn.f32x2 %0, %1, %2, %3;" : "=l"(d) : "l"(a), "l"(b), "l"(c));
    return d;
}
__device__ __forceinline__ unsigned long long dup2(float v) {
    unsigned long long d;
    asm("mov.b64 %0, {%1, %2};" : "=l"(d) : "f"(v), "f"(v));
    return d;
}
__device__ __forceinline__ void unpack2(unsigned long long v, float& lo, float& hi) {
    asm("mov.b64 {%0, %1}, %2;" : "=f"(lo), "=f"(hi) : "l"(v));
}

// ============================================================================
// K0: weight prep. g_wk[c][0..7] = 0.25*sum_j w_down[4k+j][c];
//     g_wk[c][8..15] = w_cls[k][c]; g_wk[c][16..23] = w_cls[k][C+c].
// ============================================================================
__global__ void k0_prep(const float* __restrict__ w_down,
                        const float* __restrict__ w_cls) {
    int c = blockIdx.x * blockDim.x + threadIdx.x;
    if (c >= C_DIM) return;
    float* w = &g_wk[c * NOUT];
#pragma unroll
    for (int k = 0; k < NC; ++k) {
        float s = 0.f;
#pragma unroll
        for (int j = 0; j < NM; ++j) s += w_down[(k * NM + j) * C_DIM + c];
        w[k] = 0.25f * s;
        w[8 + k]  = w_cls[k * 2 * C_DIM + c];
        w[16 + k] = w_cls[k * 2 * C_DIM + C_DIM + c];
    }
}

// ============================================================================
// K1: fused streaming pass. grid (98, SLABS), 256 threads.
// Thread owns global index g = b*196+p; accumulates 24 outputs over 512
// channels of its slab using packed f32x2 FMA (k-pairs packed, x duplicated).
// Writes 24 slab-partials. No cross-thread communication at all.
// ============================================================================
__global__ void __launch_bounds__(256) k1_main(const float* __restrict__ x) {
    __shared__ float wsh[CSLAB * NOUT];   // 512*24*4 = 48 KB

    const int slab = blockIdx.y;
    const int t = threadIdx.x;
    const int g = blockIdx.x * 256 + t;
    const int b = g / HW;
    const int p = g - b * HW;

    // stage slab weights (12288 floats) via float4
    {
        const float4* src = (const float4*)&g_wk[slab * CSLAB * NOUT];
        float4* dst = (float4*)wsh;
#pragma unroll
        for (int i = 0; i < (CSLAB * NOUT / 4) / 256; ++i)
            dst[t + i * 256] = src[t + i * 256];
    }
    __syncthreads();

    unsigned long long acc[12];
#pragma unroll
    for (int j = 0; j < 12; ++j) acc[j] = dup2(0.f);

    const float* xp = x + (size_t)b * C_DIM * HW + (size_t)(slab * CSLAB) * HW + p;

#pragma unroll 4
    for (int c = 0; c < CSLAB; ++c) {
        float xv = xp[c * HW];
        unsigned long long xx = dup2(xv);
        const ulonglong2* w = (const ulonglong2*)&wsh[c * NOUT];
#pragma unroll
        for (int j = 0; j < 6; ++j) {
            ulonglong2 wv = w[j];                 // LDS.128: 2 packed k-pairs
            acc[2 * j]     = fma2(xx, wv.x, acc[2 * j]);
            acc[2 * j + 1] = fma2(xx, wv.y, acc[2 * j + 1]);
        }
    }

    // write 24 slab-partials, coalesced per output row
    float* base = &g_part[(size_t)slab * NOUT * PART_N + g];
#pragma unroll
    for (int j = 0; j < 12; ++j) {
        float lo, hi;
        unpack2(acc[j], lo, hi);
        base[(2 * j) * PART_N]     = lo;
        base[(2 * j + 1) * PART_N] = hi;
    }
}

// ============================================================================
// K2: per-batch epilogue. 128 blocks x 224 threads (196 active pixels).
//   m_c[k,p] = sum_s A_part + beff[k]   -> out_mc, smem
//   v[k] = mean_p m_c                    -> out_v
//   m[p] = (1/8) sum_k v[k] m_c[k,p]     -> out_m
//   output[k] = (1/HW) sum_p (Z[k,p] + m[p]*Y[k,p]) + b_cls[k]
// ============================================================================
__global__ void __launch_bounds__(224) k2_epi(
    const float* __restrict__ b_down,
    const float* __restrict__ b_cls,
    float* __restrict__ out_v,
    float* __restrict__ out_output,
    float* __restrict__ out_m,
    float* __restrict__ out_mc) {
    __shared__ float red[NC * 200];   // m_c staging, padded rows
    __shared__ float vsh[NC];
    __shared__ float besh[NC];
    __shared__ float wpart[7][NC];

    const int b = blockIdx.x;
    const int t = threadIdx.x;
    const int g0 = b * HW;

    if (t < NC)
        besh[t] = 0.25f * (b_down[4 * t] + b_down[4 * t + 1] +
                           b_down[4 * t + 2] + b_down[4 * t + 3]);
    __syncthreads();

    if (t < HW) {
#pragma unroll
        for (int k = 0; k < NC; ++k) {
            float a = 0.f;
#pragma unroll
            for (int s = 0; s < SLABS; ++s)
                a += g_part[((size_t)s * NOUT + k) * PART_N + g0 + t];
            float mc = a + besh[k];
            red[k * 200 + t] = mc;
            out_mc[((size_t)b * NC + k) * HW + t] = mc;
        }
    }
    __syncthreads();

    if (t < NC) {
        float s = 0.f;
        for (int p = 0; p < HW; ++p) s += red[t * 200 + p];
        float vv = s * (1.0f / (float)HW);
        vsh[t] = vv;
        out_v[b * NC + t] = vv;
    }
    __syncthreads();

    float m = 0.f;
    if (t < HW) {
#pragma unroll
        for (int k = 0; k < NC; ++k) m = fmaf(vsh[k], red[k * 200 + t], m);
        m *= (1.0f / (float)NC);
        out_m[b * HW + t] = m;
    }

    // per-thread partial of output: Z + m*Y
    float po[NC];
#pragma unroll
    for (int k = 0; k < NC; ++k) po[k] = 0.f;
    if (t < HW) {
#pragma unroll
        for (int k = 0; k < NC; ++k) {
            float z = 0.f, y = 0.f;
#pragma unroll
            for (int s = 0; s < SLABS; ++s) {
                z += g_part[((size_t)s * NOUT + 8 + k) * PART_N + g0 + t];
                y += g_part[((size_t)s * NOUT + 16 + k) * PART_N + g0 + t];
            }
            po[k] = z + m * y;
        }
    }
#pragma unroll
    for (int o = 16; o; o >>= 1) {
#pragma unroll
        for (int k = 0; k < NC; ++k)
            po[k] += __shfl_down_sync(0xffffffffu, po[k], o);
    }
    const int lane = t & 31, warp = t >> 5;
    if (lane == 0) {
#pragma unroll
        for (int k = 0; k < NC; ++k) wpart[warp][k] = po[k];
    }
    __syncthreads();
    if (t < NC) {
        float s = 0.f;
#pragma unroll
        for (int w = 0; w < 7; ++w) s += wpart[w][t];
        out_output[b * NC + t] = s * (1.0f / (float)HW) + b_cls[t];
    }
}

// ============================================================================
// kernel_launch: 3 launches, graph-capturable, deterministic.
// Output layout: v[128,8]@0, output[128,8]@1024, m[128,196]@2048,
//                m_c[128,8,196]@27136.
// ============================================================================
extern "C" void kernel_launch(void* const* d_in, const int* in_sizes, int n_in,
                              void* d_out, int out_size) {
    const float* x      = (const float*)d_in[0];
    const float* w_down = (const float*)d_in[1];
    const float* b_down = (const float*)d_in[2];
    const float* w_cls  = (const float*)d_in[3];
    const float* b_cls  = (const float*)d_in[4];

    float* out        = (float*)d_out;
    float* out_v      = out;
    float* out_output = out + 1024;
    float* out_m      = out + 2048;
    float* out_mc     = out + 27136;

    k0_prep<<<8, 256>>>(w_down, w_cls);
    k1_main<<<dim3(PART_N / 256, SLABS), 256>>>(x);
    k2_epi<<<B_DIM, 224>>>(b_down, b_cls, out_v, out_output, out_m, out_mc);
}

// round 3
// speedup vs baseline: 1.9903x; 1.0584x over previous
#include <cuda_runtime.h>

#define B_DIM 128
#define C_DIM 2048
#define HW 196
#define NC 8
#define NM 4
#define NOUT 24                    // 8 A (m_c pre-bias) + 8 Z + 8 Y
#define PART_N (B_DIM * HW)        // 25088 global pixel-batch indices
#define SLABS 4
#define CSLAB (C_DIM / SLABS)      // 512

// ---- scratch (__device__ globals; no allocation allowed) ----
// weights, per channel 24 floats: [0..7]=w_eff, [8..15]=w_cls[:, :C], [16..23]=w_cls[:, C:]
__device__ float g_wk[C_DIM * NOUT];
// slab-partial per-pixel outputs: [slab][out24][g]
__device__ float g_part[SLABS * NOUT * PART_N];

// ---------------- packed f32x2 helpers ----------------
__device__ __forceinline__ unsigned long long fma2(
    unsigned long long a, unsigned long long b, unsigned long long c) {
    unsigned long long d;
    asm("fma.rn.f32x2 %0, %1, %2, %3;" : "=l"(d) : "l"(a), "l"(b), "l"(c));
    return d;
}
__device__ __forceinline__ unsigned long long dup2(float v) {
    unsigned long long d;
    asm("mov.b64 %0, {%1, %2};" : "=l"(d) : "f"(v), "f"(v));
    return d;
}
__device__ __forceinline__ void unpack2(unsigned long long v, float& lo, float& hi) {
    asm("mov.b64 {%0, %1}, %2;" : "=f"(lo), "=f"(hi) : "l"(v));
}

// ============================================================================
// K0: weight prep, parallel over (c, k). grid (8, 8) x 256.
// g_wk[c][k]      = 0.25 * sum_j w_down[(4k+j)*C + c]
// g_wk[c][8+k]    = w_cls[k][c]
// g_wk[c][16+k]   = w_cls[k][C + c]
// ============================================================================
__global__ void __launch_bounds__(256) k0_prep(const float* __restrict__ w_down,
                                               const float* __restrict__ w_cls) {
    const int c = blockIdx.x * 256 + threadIdx.x;
    const int k = blockIdx.y;
    float s0 = w_down[(k * NM + 0) * C_DIM + c];
    float s1 = w_down[(k * NM + 1) * C_DIM + c];
    float s2 = w_down[(k * NM + 2) * C_DIM + c];
    float s3 = w_down[(k * NM + 3) * C_DIM + c];
    float z  = w_cls[k * 2 * C_DIM + c];
    float y  = w_cls[k * 2 * C_DIM + C_DIM + c];
    g_wk[c * NOUT + k]      = 0.25f * ((s0 + s1) + (s2 + s3));
    g_wk[c * NOUT + 8 + k]  = z;
    g_wk[c * NOUT + 16 + k] = y;
}

// ============================================================================
// K1: fused streaming pass. grid (98, SLABS), 256 threads, 4 blocks/SM.
// Thread owns global index g = b*196+p; accumulates 24 outputs over 512
// channels of its slab using packed f32x2 FMA (k-pairs packed, x duplicated).
// 8 channels of x batched per iteration -> 8 LDGs in flight per thread.
// ============================================================================
__global__ void __launch_bounds__(256, 4) k1_main(const float* __restrict__ x) {
    __shared__ float wsh[CSLAB * NOUT];   // 48 KB

    const int slab = blockIdx.y;
    const int t = threadIdx.x;
    const int g = blockIdx.x * 256 + t;
    const int b = g / HW;
    const int p = g - b * HW;

    // stage slab weights (12288 floats) via float4
    {
        const float4* src = (const float4*)&g_wk[slab * CSLAB * NOUT];
        float4* dst = (float4*)wsh;
#pragma unroll
        for (int i = 0; i < (CSLAB * NOUT / 4) / 256; ++i)
            dst[t + i * 256] = src[t + i * 256];
    }
    __syncthreads();

    unsigned long long acc[12];
#pragma unroll
    for (int j = 0; j < 12; ++j) acc[j] = dup2(0.f);

    const float* xp = x + (size_t)b * C_DIM * HW + (size_t)(slab * CSLAB) * HW + p;

#pragma unroll 1
    for (int c0 = 0; c0 < CSLAB; c0 += 8) {
        // front-batch 8 independent global loads (MLP = 8)
        float xv[8];
#pragma unroll
        for (int u = 0; u < 8; ++u) xv[u] = __ldg(&xp[(c0 + u) * HW]);
#pragma unroll
        for (int u = 0; u < 8; ++u) {
            unsigned long long xx = dup2(xv[u]);
            const ulonglong2* w = (const ulonglong2*)&wsh[(c0 + u) * NOUT];
            ulonglong2 w0 = w[0];
            ulonglong2 w1 = w[1];
            ulonglong2 w2 = w[2];
            acc[0]  = fma2(xx, w0.x, acc[0]);
            acc[1]  = fma2(xx, w0.y, acc[1]);
            acc[2]  = fma2(xx, w1.x, acc[2]);
            acc[3]  = fma2(xx, w1.y, acc[3]);
            acc[4]  = fma2(xx, w2.x, acc[4]);
            acc[5]  = fma2(xx, w2.y, acc[5]);
            const ulonglong2* w_ = w + 3;
            ulonglong2 w3 = w_[0];
            ulonglong2 w4 = w_[1];
            ulonglong2 w5 = w_[2];
            acc[6]  = fma2(xx, w3.x, acc[6]);
            acc[7]  = fma2(xx, w3.y, acc[7]);
            acc[8]  = fma2(xx, w4.x, acc[8]);
            acc[9]  = fma2(xx, w4.y, acc[9]);
            acc[10] = fma2(xx, w5.x, acc[10]);
            acc[11] = fma2(xx, w5.y, acc[11]);
        }
    }

    // write 24 slab-partials, coalesced per output row
    float* base = &g_part[(size_t)slab * NOUT * PART_N + g];
#pragma unroll
    for (int j = 0; j < 12; ++j) {
        float lo, hi;
        unpack2(acc[j], lo, hi);
        base[(2 * j) * PART_N]     = lo;
        base[(2 * j + 1) * PART_N] = hi;
    }
}

// ============================================================================
// K2: per-batch epilogue. 128 blocks x 224 threads (196 active pixels).
//   m_c[k,p] = sum_s A_part + beff[k]   -> out_mc, smem
//   v[k] = mean_p m_c                    -> out_v
//   m[p] = (1/8) sum_k v[k] m_c[k,p]     -> out_m
//   output[k] = (1/HW) sum_p (Z[k,p] + m[p]*Y[k,p]) + b_cls[k]
// ============================================================================
__global__ void __launch_bounds__(224) k2_epi(
    const float* __restrict__ b_down,
    const float* __restrict__ b_cls,
    float* __restrict__ out_v,
    float* __restrict__ out_output,
    float* __restrict__ out_m,
    float* __restrict__ out_mc) {
    __shared__ float red[NC * 200];   // m_c staging, padded rows
    __shared__ float vsh[NC];
    __shared__ float besh[NC];
    __shared__ float wpart[7][NC];

    const int b = blockIdx.x;
    const int t = threadIdx.x;
    const int g0 = b * HW;

    if (t < NC)
        besh[t] = 0.25f * (b_down[4 * t] + b_down[4 * t + 1] +
                           b_down[4 * t + 2] + b_down[4 * t + 3]);
    __syncthreads();

    if (t < HW) {
#pragma unroll
        for (int k = 0; k < NC; ++k) {
            float a = 0.f;
#pragma unroll
            for (int s = 0; s < SLABS; ++s)
                a += g_part[((size_t)s * NOUT + k) * PART_N + g0 + t];
            float mc = a + besh[k];
            red[k * 200 + t] = mc;
            out_mc[((size_t)b * NC + k) * HW + t] = mc;
        }
    }
    __syncthreads();

    if (t < NC) {
        float s = 0.f;
        for (int p = 0; p < HW; ++p) s += red[t * 200 + p];
        float vv = s * (1.0f / (float)HW);
        vsh[t] = vv;
        out_v[b * NC + t] = vv;
    }
    __syncthreads();

    float m = 0.f;
    if (t < HW) {
#pragma unroll
        for (int k = 0; k < NC; ++k) m = fmaf(vsh[k], red[k * 200 + t], m);
        m *= (1.0f / (float)NC);
        out_m[b * HW + t] = m;
    }

    // per-thread partial of output: Z + m*Y
    float po[NC];
#pragma unroll
    for (int k = 0; k < NC; ++k) po[k] = 0.f;
    if (t < HW) {
#pragma unroll
        for (int k = 0; k < NC; ++k) {
            float z = 0.f, y = 0.f;
#pragma unroll
            for (int s = 0; s < SLABS; ++s) {
                z += g_part[((size_t)s * NOUT + 8 + k) * PART_N + g0 + t];
                y += g_part[((size_t)s * NOUT + 16 + k) * PART_N + g0 + t];
            }
            po[k] = z + m * y;
        }
    }
#pragma unroll
    for (int o = 16; o; o >>= 1) {
#pragma unroll
        for (int k = 0; k < NC; ++k)
            po[k] += __shfl_down_sync(0xffffffffu, po[k], o);
    }
    const int lane = t & 31, warp = t >> 5;
    if (lane == 0) {
#pragma unroll
        for (int k = 0; k < NC; ++k) wpart[warp][k] = po[k];
    }
    __syncthreads();
    if (t < NC) {
        float s = 0.f;
#pragma unroll
        for (int w = 0; w < 7; ++w) s += wpart[w][t];
        out_output[b * NC + t] = s * (1.0f / (float)HW) + b_cls[t];
    }
}

// ============================================================================
// kernel_launch: 3 launches, graph-capturable, deterministic.
// Output layout: v[128,8]@0, output[128,8]@1024, m[128,196]@2048,
//                m_c[128,8,196]@27136.
// ============================================================================
extern "C" void kernel_launch(void* const* d_in, const int* in_sizes, int n_in,
                              void* d_out, int out_size) {
    const float* x      = (const float*)d_in[0];
    const float* w_down = (const float*)d_in[1];
    const float* b_down = (const float*)d_in[2];
    const float* w_cls  = (const float*)d_in[3];
    const float* b_cls  = (const float*)d_in[4];

    float* out        = (float*)d_out;
    float* out_v      = out;
    float* out_output = out + 1024;
    float* out_m      = out + 2048;
    float* out_mc     = out + 27136;

    k0_prep<<<dim3(8, 8), 256>>>(w_down, w_cls);
    k1_main<<<dim3(PART_N / 256, SLABS), 256>>>(x);
    k2_epi<<<B_DIM, 224>>>(b_down, b_cls, out_v, out_output, out_m, out_mc);
}